// round 13
// baseline (speedup 1.0000x reference)
#include <cuda_runtime.h>
#include <cuda_bf16.h>

#define NEGV (-1e30f)

// ---------------- scratch (no allocations allowed) ----------------
__device__ float g_rp[256 * 12 * 4 * 512];   // roipool stage-1 partials (12 chunks of 2 rows)
__device__ float g_part1[16 * 256 * 200];    // FC1 split-K partials

__device__ __forceinline__ float4 fmax4(float4 a, float4 b) {
    return make_float4(fmaxf(a.x, b.x), fmaxf(a.y, b.y),
                       fmaxf(a.z, b.z), fmaxf(a.w, b.w));
}

// packed f32x2 helpers (FFMA2 path — only reachable via PTX)
__device__ __forceinline__ unsigned long long dup2(float b) {
    unsigned long long r;
    asm("mov.b64 %0, {%1, %1};" : "=l"(r) : "f"(b));
    return r;
}
__device__ __forceinline__ void ffma2(unsigned long long& acc,
                                      unsigned long long a,
                                      unsigned long long b) {
    asm("fma.rn.f32x2 %0, %1, %2, %3;" : "=l"(acc) : "l"(a), "l"(b), "l"(acc));
}
__device__ __forceinline__ float2 unpack2(unsigned long long v) {
    float lo, hi;
    asm("mov.b64 {%0, %1}, %2;" : "=f"(lo), "=f"(hi) : "l"(v));
    return make_float2(lo, hi);
}

// ---------------- Kernel A: ROI pool stage 1 (2-row chunk x col-bin) -------
// grid = (256 proposals, 12 row-chunks of 2, 2 col-bins), block = 128 (float4)
// z=0 computes row-bins over cols [0,e0c); z=1 over [s1c,w).
// Feature-map accesses provably in-bounds (ey<=76, ex<=128; forced h,w=2
// cases keep sy+1<=75, sx+1<=127).
__global__ void roipool_stage1(const float* __restrict__ fm,
                               const int* __restrict__ coords,
                               float* __restrict__ rp) {
    const int p = blockIdx.x;
    const int ci = blockIdx.y;
    const int cb = blockIdx.z;     // column bin
    const int tid = threadIdx.x;

    const int y0 = coords[p * 4 + 0];
    const int x0 = coords[p * 4 + 1];
    const int y1 = coords[p * 4 + 2];
    const int x1 = coords[p * 4 + 3];

    const int sy = min(y0 / 8, 74);
    const int sx = min(x0 / 8, 126);
    const int ey = (y1 + 7) / 8;
    const int ex = (x1 + 7) / 8;
    const int h = max(ey - sy, 2);     // <= 24
    const int w = max(ex - sx, 2);     // <= 24

    const int r0 = ci * 2;
    if (r0 >= h) return;               // inactive chunk; consumer skips it
    const int r1 = min(r0 + 2, h);

    const int e0r = (h + 1) / 2;       // row bin0: [0, e0r)
    const int s1r = h / 2;             // row bin1: [s1r, h)
    // column range for this block's bin
    const int c0 = (cb == 0) ? 0 : (w / 2);
    const int c1 = (cb == 0) ? ((w + 1) / 2) : w;

    float4 m0 = make_float4(NEGV, NEGV, NEGV, NEGV);   // row-bin0 x this col-bin
    float4 m1 = m0;                                     // row-bin1 x this col-bin

    for (int r = r0; r < r1; r++) {
        const float* rowbase = fm + ((size_t)((sy + r) * 128 + sx)) * 512 + 4 * tid;

        float4 cm = make_float4(NEGV, NEGV, NEGV, NEGV);
        #pragma unroll 6
        for (int c = c0; c < c1; c++) {
            cm = fmax4(cm, *reinterpret_cast<const float4*>(rowbase + (size_t)c * 512));
        }

        if (r < e0r)  m0 = fmax4(m0, cm);
        if (r >= s1r) m1 = fmax4(m1, cm);
    }

    // bin index = rowbin*2 + colbin
    float* outp = rp + ((size_t)(p * 12 + ci) * 4) * 512 + 4 * tid;
    *reinterpret_cast<float4*>(outp + (size_t)(0 + cb) * 512) = m0;
    *reinterpret_cast<float4*>(outp + (size_t)(2 + cb) * 512) = m1;
}

// ---------------- Kernel B: FC1 split-K partial GEMM (+fused chunk reduce) --
// A = pooled [256,2048] materialized on the fly from rp; B = W1 (original
// layout, coalesced across warp). grid = (32 mtiles, 16 K-splits), 200 thr.
__global__ void fc1_partial(const int* __restrict__ coords,
                            const float* __restrict__ rp,
                            const float* __restrict__ W1,
                            float* __restrict__ part) {
    __shared__ float As[128][8];
    __shared__ int nchs[8];
    const int mt = blockIdx.x;
    const int ks = blockIdx.y;
    const int tid = threadIdx.x;
    const int m0 = mt * 8;
    const int k0 = ks * 128;
    const int bin = k0 >> 9;       // k0/512: bin fixed within this K-slice
    const int ch0 = k0 & 511;

    if (tid < 8) {
        const int m = m0 + tid;
        const int cy0 = coords[m * 4 + 0];
        const int cy1 = coords[m * 4 + 2];
        const int sy = min(cy0 / 8, 74);
        const int ey = (cy1 + 7) / 8;
        const int h = max(ey - sy, 2);
        nchs[tid] = (h + 1) / 2;   // active 2-row chunks, 1..12
    }
    __syncthreads();

    // stage A tile: reduce rp chunks -> pooled element, transposed into smem
    for (int idx = tid; idx < 8 * 128; idx += 200) {
        const int r = idx >> 7;
        const int k = idx & 127;
        const int m = m0 + r;
        const float* bp = rp + ((size_t)(m * 12) * 4 + bin) * 512 + ch0 + k;
        float v = bp[0];
        const int nc = nchs[r];
        for (int ci = 1; ci < nc; ci++) v = fmaxf(v, bp[(size_t)ci * 2048]);
        As[k][r] = v;
    }
    __syncthreads();

    const int j = tid;
    unsigned long long acc01 = 0ull, acc23 = 0ull, acc45 = 0ull, acc67 = 0ull;

    const float* Bp = W1 + (size_t)k0 * 200 + j;
    #pragma unroll 4
    for (int kb = 0; kb < 128; kb += 8) {
        float b[8];
        #pragma unroll
        for (int u = 0; u < 8; u++) b[u] = Bp[(size_t)(kb + u) * 200];
        #pragma unroll
        for (int u = 0; u < 8; u++) {
            const unsigned long long bd = dup2(b[u]);
            const ulonglong2 lo = *reinterpret_cast<const ulonglong2*>(&As[kb + u][0]);
            const ulonglong2 hi = *reinterpret_cast<const ulonglong2*>(&As[kb + u][4]);
            ffma2(acc01, lo.x, bd);
            ffma2(acc23, lo.y, bd);
            ffma2(acc45, hi.x, bd);
            ffma2(acc67, hi.y, bd);
        }
    }

    float* out = part + ((size_t)ks * 256 + m0) * 200 + j;
    const float2 r01 = unpack2(acc01);
    const float2 r23 = unpack2(acc23);
    const float2 r45 = unpack2(acc45);
    const float2 r67 = unpack2(acc67);
    out[0 * 200] = r01.x;  out[1 * 200] = r01.y;
    out[2 * 200] = r23.x;  out[3 * 200] = r23.y;
    out[4 * 200] = r45.x;  out[5 * 200] = r45.y;
    out[6 * 200] = r67.x;  out[7 * 200] = r67.y;
}

// ---------------- Kernel C: fused reduce + FC2 + heads + decode -------------
// grid = 256 blocks (1 proposal each), block = 512 threads, K-split phases.
__global__ void fused_tail(const float* __restrict__ part,
                           const float* __restrict__ b1,
                           const float* __restrict__ W2,
                           const float* __restrict__ b2,
                           const int* __restrict__ coords,
                           const float* __restrict__ W3,
                           const float* __restrict__ b3,
                           const float* __restrict__ W4,
                           const float* __restrict__ b4,
                           float* __restrict__ out) {
    __shared__ float ph1[2][200];   // phase-1 K-split partials
    __shared__ float f1s[200];      // f1 row
    __shared__ float pp[2][200];    // FC2 K-split partials
    __shared__ float fs[200];       // f2 row
    __shared__ float wk[21 * 200];  // W3/W4 transposed into smem: wk[o*200+k]
    __shared__ float op[21][8];     // head partials
    __shared__ float os[21];        // head outputs

    const int m = blockIdx.x;
    const int tid = threadIdx.x;

    // stage W3/W4 (coalesced reads, scattered smem writes are cheap)
    for (int idx = tid; idx < 200 * 16; idx += 512) {
        const int k = idx / 16, o = idx % 16;
        wk[o * 200 + k] = W3[idx];
    }
    for (int idx = tid; idx < 200 * 5; idx += 512) {
        const int k = idx / 5, o = idx % 5;
        wk[(16 + o) * 200 + k] = W4[idx];
    }

    // ---- phase 1: split-K reduce of FC1 partials (2-way) ----
    if (tid < 400) {
        const int j = tid % 200;
        const int g = tid / 200;    // partial group 0/1
        float s = 0.f;
        const float* p0 = part + (size_t)(g * 8) * 51200 + (size_t)m * 200 + j;
        #pragma unroll
        for (int ks = 0; ks < 8; ks++) s += p0[(size_t)ks * 51200];
        ph1[g][j] = s;
    }
    __syncthreads();
    if (tid < 200) {
        f1s[tid] = fmaxf(ph1[0][tid] + ph1[1][tid] + b1[tid], 0.0f);
    }
    __syncthreads();

    // ---- phase 2: FC2 (2-way K-split, coalesced W2 loads, batched) ----
    if (tid < 400) {
        const int j = tid % 200;
        const int g = tid / 200;
        const int kb0 = g * 100;
        float acc = 0.f;
        const float* Bp = W2 + (size_t)kb0 * 200 + j;
        #pragma unroll 3
        for (int kb = 0; kb < 100; kb += 10) {
            float b[10];
            #pragma unroll
            for (int u = 0; u < 10; u++) b[u] = Bp[(size_t)(kb + u) * 200];
            #pragma unroll
            for (int u = 0; u < 10; u++) acc = fmaf(f1s[kb0 + kb + u], b[u], acc);
        }
        pp[g][j] = acc;
    }
    __syncthreads();
    if (tid < 200) {
        fs[tid] = fmaxf(pp[0][tid] + pp[1][tid] + b2[tid], 0.0f);
    }
    __syncthreads();

    // ---- phase 3: head dot products (8-way K-split, contiguous smem rows) --
    if (tid < 168) {
        const int o = tid / 8;       // 0..20
        const int ks = tid % 8;      // 0..7
        const int kb = ks * 25;
        const float* wrow = wk + o * 200 + kb;
        float s0 = 0.f, s1 = 0.f;
        #pragma unroll
        for (int k = 0; k < 24; k += 2) {
            s0 = fmaf(fs[kb + k],     wrow[k],     s0);
            s1 = fmaf(fs[kb + k + 1], wrow[k + 1], s1);
        }
        op[o][ks] = s0 + s1 + fs[kb + 24] * wrow[24];
    }
    __syncthreads();

    if (tid < 21) {
        const float bias = (tid < 16) ? b3[tid] : b4[tid - 16];
        float s = bias;
        #pragma unroll
        for (int ks = 0; ks < 8; ks++) s += op[tid][ks];
        os[tid] = s;
    }
    __syncthreads();

    // ---- phase 4: softmax / argmax / box decode ----
    if (tid == 0) {
        const float l0 = os[16], l1 = os[17], l2 = os[18], l3 = os[19], l4 = os[20];
        int cls = 0;
        float best = l0;
        if (l1 > best) { best = l1; cls = 1; }
        if (l2 > best) { best = l2; cls = 2; }
        if (l3 > best) { best = l3; cls = 3; }
        if (l4 > best) { best = l4; cls = 4; }
        const float mx = best;
        const float e0 = expf(l0 - mx), e1 = expf(l1 - mx), e2 = expf(l2 - mx),
                    e3 = expf(l3 - mx), e4 = expf(l4 - mx);
        const float sum = e0 + e1 + e2 + e3 + e4;
        const float score = fmaxf(fmaxf(e1, e2), fmaxf(e3, e4)) / sum;

        const int jj = max(cls - 1, 0);
        const float r0 = os[jj * 4 + 0];
        const float r1 = os[jj * 4 + 1];
        const float r2 = os[jj * 4 + 2];
        const float r3 = os[jj * 4 + 3];

        const float y0 = (float)coords[m * 4 + 0];
        const float x0 = (float)coords[m * 4 + 1];
        const float y1 = (float)coords[m * 4 + 2];
        const float x1 = (float)coords[m * 4 + 3];
        const float ph = y1 - y0;
        const float pw = x1 - x0;
        const float py = y0 + 0.5f * ph;
        const float px = x0 + 0.5f * pw;

        out[m * 4 + 0] = fmaf(ph, r0, py);
        out[m * 4 + 1] = fmaf(pw, r1, px);
        out[m * 4 + 2] = ph * fminf(fmaxf(expf(r2), 0.001f), 20.0f);
        out[m * 4 + 3] = pw * fminf(fmaxf(expf(r3), 0.001f), 20.0f);
        out[1024 + m] = score;
        out[1280 + m] = (cls != 0) ? 1.0f : 0.0f;
    }
}

// ---------------- launch ----------------
extern "C" void kernel_launch(void* const* d_in, const int* in_sizes, int n_in,
                              void* d_out, int out_size) {
    const float* fm     = (const float*)d_in[0];
    const int*   coords = (const int*)d_in[1];
    const float* W1 = (const float*)d_in[2];
    const float* b1 = (const float*)d_in[3];
    const float* W2 = (const float*)d_in[4];
    const float* b2 = (const float*)d_in[5];
    const float* W3 = (const float*)d_in[6];
    const float* b3 = (const float*)d_in[7];
    const float* W4 = (const float*)d_in[8];
    const float* b4 = (const float*)d_in[9];
    float* out = (float*)d_out;

    float *rp = nullptr, *part1 = nullptr;
    cudaGetSymbolAddress((void**)&rp, g_rp);
    cudaGetSymbolAddress((void**)&part1, g_part1);

    roipool_stage1<<<dim3(256, 12, 2), 128>>>(fm, coords, rp);
    fc1_partial<<<dim3(32, 16), 200>>>(coords, rp, W1, part1);
    fused_tail<<<256, 512>>>(part1, b1, W2, b2, coords, W3, b3, W4, b4, out);
}

// round 14
// speedup vs baseline: 1.0683x; 1.0683x over previous
#include <cuda_runtime.h>
#include <cuda_bf16.h>

#define NEGV (-1e30f)

// ---------------- scratch (no allocations allowed) ----------------
__device__ float g_rp[256 * 12 * 4 * 512];   // roipool partials (12 chunks of 2 rows)
__device__ float g_part1[32 * 256 * 200];    // FC1 split-K partials

__device__ __forceinline__ float4 fmax4(float4 a, float4 b) {
    return make_float4(fmaxf(a.x, b.x), fmaxf(a.y, b.y),
                       fmaxf(a.z, b.z), fmaxf(a.w, b.w));
}

// packed f32x2 helpers (FFMA2 path — only reachable via PTX)
__device__ __forceinline__ unsigned long long dup2(float b) {
    unsigned long long r;
    asm("mov.b64 %0, {%1, %1};" : "=l"(r) : "f"(b));
    return r;
}
__device__ __forceinline__ void ffma2(unsigned long long& acc,
                                      unsigned long long a,
                                      unsigned long long b) {
    asm("fma.rn.f32x2 %0, %1, %2, %3;" : "=l"(acc) : "l"(a), "l"(b), "l"(acc));
}
__device__ __forceinline__ float2 unpack2(unsigned long long v) {
    float lo, hi;
    asm("mov.b64 {%0, %1}, %2;" : "=f"(lo), "=f"(hi) : "l"(v));
    return make_float2(lo, hi);
}

// ---------------- Kernel A: ROI pool stage 1 (2-row chunk x col-bin) -------
// grid = (256 proposals, 12 row-chunks of 2, 2 col-bins), block = 128 (float4)
// Inactive chunks write NEGV so the consumer can reduce a FIXED 12 chunks.
// Feature-map accesses provably in-bounds (ey<=76, ex<=128; forced h,w=2
// cases keep sy+1<=75, sx+1<=127).
__global__ void roipool_stage1(const float* __restrict__ fm,
                               const int* __restrict__ coords,
                               float* __restrict__ rp) {
    const int p = blockIdx.x;
    const int ci = blockIdx.y;
    const int cb = blockIdx.z;     // column bin
    const int tid = threadIdx.x;

    const int y0 = coords[p * 4 + 0];
    const int x0 = coords[p * 4 + 1];
    const int y1 = coords[p * 4 + 2];
    const int x1 = coords[p * 4 + 3];

    const int sy = min(y0 / 8, 74);
    const int sx = min(x0 / 8, 126);
    const int ey = (y1 + 7) / 8;
    const int ex = (x1 + 7) / 8;
    const int h = max(ey - sy, 2);     // <= 24
    const int w = max(ex - sx, 2);     // <= 24

    float* outp = rp + ((size_t)(p * 12 + ci) * 4) * 512 + 4 * tid;

    const int r0 = ci * 2;
    float4 m0 = make_float4(NEGV, NEGV, NEGV, NEGV);   // row-bin0 x this col-bin
    float4 m1 = m0;                                     // row-bin1 x this col-bin

    if (r0 < h) {
        const int r1 = min(r0 + 2, h);
        const int e0r = (h + 1) / 2;       // row bin0: [0, e0r)
        const int s1r = h / 2;             // row bin1: [s1r, h)
        const int c0 = (cb == 0) ? 0 : (w / 2);
        const int c1 = (cb == 0) ? ((w + 1) / 2) : w;

        for (int r = r0; r < r1; r++) {
            const float* rowbase = fm + ((size_t)((sy + r) * 128 + sx)) * 512 + 4 * tid;
            float4 cm = make_float4(NEGV, NEGV, NEGV, NEGV);
            #pragma unroll 6
            for (int c = c0; c < c1; c++) {
                cm = fmax4(cm, *reinterpret_cast<const float4*>(rowbase + (size_t)c * 512));
            }
            if (r < e0r)  m0 = fmax4(m0, cm);
            if (r >= s1r) m1 = fmax4(m1, cm);
        }
    }

    // bin index = rowbin*2 + colbin  (inactive chunks store NEGV)
    *reinterpret_cast<float4*>(outp + (size_t)(0 + cb) * 512) = m0;
    *reinterpret_cast<float4*>(outp + (size_t)(2 + cb) * 512) = m1;
}

// ---------------- Kernel B: FC1 split-K partial GEMM (+fixed chunk reduce) --
// A = pooled [256,2048] materialized on the fly from rp (12-chunk unrolled
// max); B = W1 (original layout, coalesced across warp).
// grid = (32 mtiles of 8 rows, 32 K-splits of 64), block = 200 threads.
__global__ void fc1_partial(const float* __restrict__ rp,
                            const float* __restrict__ W1,
                            float* __restrict__ part) {
    __shared__ float As[64][8];
    const int mt = blockIdx.x;
    const int ks = blockIdx.y;
    const int tid = threadIdx.x;
    const int m0 = mt * 8;
    const int k0 = ks * 64;
    const int bin = k0 >> 9;       // k0/512: bin fixed within this K-slice
    const int ch0 = k0 & 511;

    // stage A tile: fixed 12-chunk batched max -> pooled element (transposed)
    for (int idx = tid; idx < 8 * 64; idx += 200) {
        const int r = idx >> 6;
        const int k = idx & 63;
        const int m = m0 + r;
        const float* bp = rp + ((size_t)(m * 12) * 4 + bin) * 512 + ch0 + k;
        float v[12];
        #pragma unroll
        for (int ci = 0; ci < 12; ci++) v[ci] = bp[(size_t)ci * 2048];
        float mx = v[0];
        #pragma unroll
        for (int ci = 1; ci < 12; ci++) mx = fmaxf(mx, v[ci]);
        As[k][r] = mx;
    }
    __syncthreads();

    const int j = tid;
    unsigned long long acc01 = 0ull, acc23 = 0ull, acc45 = 0ull, acc67 = 0ull;

    const float* Bp = W1 + (size_t)k0 * 200 + j;
    #pragma unroll
    for (int kb = 0; kb < 64; kb += 8) {
        float b[8];
        #pragma unroll
        for (int u = 0; u < 8; u++) b[u] = Bp[(size_t)(kb + u) * 200];
        #pragma unroll
        for (int u = 0; u < 8; u++) {
            const unsigned long long bd = dup2(b[u]);
            const ulonglong2 lo = *reinterpret_cast<const ulonglong2*>(&As[kb + u][0]);
            const ulonglong2 hi = *reinterpret_cast<const ulonglong2*>(&As[kb + u][4]);
            ffma2(acc01, lo.x, bd);
            ffma2(acc23, lo.y, bd);
            ffma2(acc45, hi.x, bd);
            ffma2(acc67, hi.y, bd);
        }
    }

    float* out = part + ((size_t)ks * 256 + m0) * 200 + j;
    const float2 r01 = unpack2(acc01);
    const float2 r23 = unpack2(acc23);
    const float2 r45 = unpack2(acc45);
    const float2 r67 = unpack2(acc67);
    out[0 * 200] = r01.x;  out[1 * 200] = r01.y;
    out[2 * 200] = r23.x;  out[3 * 200] = r23.y;
    out[4 * 200] = r45.x;  out[5 * 200] = r45.y;
    out[6 * 200] = r67.x;  out[7 * 200] = r67.y;
}

// ---------------- Kernel C: fused reduce + FC2 + heads + decode -------------
// grid = 256 blocks (1 proposal each), block = 512 threads, K-split phases.
__global__ void fused_tail(const float* __restrict__ part,
                           const float* __restrict__ b1,
                           const float* __restrict__ W2,
                           const float* __restrict__ b2,
                           const int* __restrict__ coords,
                           const float* __restrict__ W3,
                           const float* __restrict__ b3,
                           const float* __restrict__ W4,
                           const float* __restrict__ b4,
                           float* __restrict__ out) {
    __shared__ float ph1[2][200];   // phase-1 K-split partials
    __shared__ float f1s[200];      // f1 row
    __shared__ float pp[2][200];    // FC2 K-split partials
    __shared__ float fs[200];       // f2 row
    __shared__ float wk[21 * 200];  // W3/W4 transposed into smem: wk[o*200+k]
    __shared__ float op[21][8];     // head partials
    __shared__ float os[21];        // head outputs

    const int m = blockIdx.x;
    const int tid = threadIdx.x;

    // stage W3/W4 (coalesced reads, scattered smem writes are cheap)
    for (int idx = tid; idx < 200 * 16; idx += 512) {
        const int k = idx / 16, o = idx % 16;
        wk[o * 200 + k] = W3[idx];
    }
    for (int idx = tid; idx < 200 * 5; idx += 512) {
        const int k = idx / 5, o = idx % 5;
        wk[(16 + o) * 200 + k] = W4[idx];
    }

    // ---- phase 1: split-K reduce of FC1 partials (2 groups x 16 slabs) ----
    if (tid < 400) {
        const int j = tid % 200;
        const int g = tid / 200;    // partial group 0/1
        const float* p0 = part + (size_t)(g * 16) * 51200 + (size_t)m * 200 + j;
        float b[16];
        #pragma unroll
        for (int ks = 0; ks < 16; ks++) b[ks] = p0[(size_t)ks * 51200];
        float s = 0.f;
        #pragma unroll
        for (int ks = 0; ks < 16; ks++) s += b[ks];
        ph1[g][j] = s;
    }
    __syncthreads();
    if (tid < 200) {
        f1s[tid] = fmaxf(ph1[0][tid] + ph1[1][tid] + b1[tid], 0.0f);
    }
    __syncthreads();

    // ---- phase 2: FC2 (2-way K-split, coalesced W2 loads, 20-wide batch) --
    if (tid < 400) {
        const int j = tid % 200;
        const int g = tid / 200;
        const int kb0 = g * 100;
        float acc = 0.f;
        const float* Bp = W2 + (size_t)kb0 * 200 + j;
        #pragma unroll
        for (int kb = 0; kb < 100; kb += 20) {
            float b[20];
            #pragma unroll
            for (int u = 0; u < 20; u++) b[u] = Bp[(size_t)(kb + u) * 200];
            #pragma unroll
            for (int u = 0; u < 20; u++) acc = fmaf(f1s[kb0 + kb + u], b[u], acc);
        }
        pp[g][j] = acc;
    }
    __syncthreads();
    if (tid < 200) {
        fs[tid] = fmaxf(pp[0][tid] + pp[1][tid] + b2[tid], 0.0f);
    }
    __syncthreads();

    // ---- phase 3: head dot products (8-way K-split, contiguous smem rows) --
    if (tid < 168) {
        const int o = tid / 8;       // 0..20
        const int ks = tid % 8;      // 0..7
        const int kb = ks * 25;
        const float* wrow = wk + o * 200 + kb;
        float s0 = 0.f, s1 = 0.f;
        #pragma unroll
        for (int k = 0; k < 24; k += 2) {
            s0 = fmaf(fs[kb + k],     wrow[k],     s0);
            s1 = fmaf(fs[kb + k + 1], wrow[k + 1], s1);
        }
        op[o][ks] = s0 + s1 + fs[kb + 24] * wrow[24];
    }
    __syncthreads();

    if (tid < 21) {
        const float bias = (tid < 16) ? b3[tid] : b4[tid - 16];
        float s = bias;
        #pragma unroll
        for (int ks = 0; ks < 8; ks++) s += op[tid][ks];
        os[tid] = s;
    }
    __syncthreads();

    // ---- phase 4: softmax / argmax / box decode ----
    if (tid == 0) {
        const float l0 = os[16], l1 = os[17], l2 = os[18], l3 = os[19], l4 = os[20];
        int cls = 0;
        float best = l0;
        if (l1 > best) { best = l1; cls = 1; }
        if (l2 > best) { best = l2; cls = 2; }
        if (l3 > best) { best = l3; cls = 3; }
        if (l4 > best) { best = l4; cls = 4; }
        const float mx = best;
        const float e0 = expf(l0 - mx), e1 = expf(l1 - mx), e2 = expf(l2 - mx),
                    e3 = expf(l3 - mx), e4 = expf(l4 - mx);
        const float sum = e0 + e1 + e2 + e3 + e4;
        const float score = fmaxf(fmaxf(e1, e2), fmaxf(e3, e4)) / sum;

        const int jj = max(cls - 1, 0);
        const float r0 = os[jj * 4 + 0];
        const float r1 = os[jj * 4 + 1];
        const float r2 = os[jj * 4 + 2];
        const float r3 = os[jj * 4 + 3];

        const float y0 = (float)coords[m * 4 + 0];
        const float x0 = (float)coords[m * 4 + 1];
        const float y1 = (float)coords[m * 4 + 2];
        const float x1 = (float)coords[m * 4 + 3];
        const float ph = y1 - y0;
        const float pw = x1 - x0;
        const float py = y0 + 0.5f * ph;
        const float px = x0 + 0.5f * pw;

        out[m * 4 + 0] = fmaf(ph, r0, py);
        out[m * 4 + 1] = fmaf(pw, r1, px);
        out[m * 4 + 2] = ph * fminf(fmaxf(expf(r2), 0.001f), 20.0f);
        out[m * 4 + 3] = pw * fminf(fmaxf(expf(r3), 0.001f), 20.0f);
        out[1024 + m] = score;
        out[1280 + m] = (cls != 0) ? 1.0f : 0.0f;
    }
}

// ---------------- launch ----------------
extern "C" void kernel_launch(void* const* d_in, const int* in_sizes, int n_in,
                              void* d_out, int out_size) {
    const float* fm     = (const float*)d_in[0];
    const int*   coords = (const int*)d_in[1];
    const float* W1 = (const float*)d_in[2];
    const float* b1 = (const float*)d_in[3];
    const float* W2 = (const float*)d_in[4];
    const float* b2 = (const float*)d_in[5];
    const float* W3 = (const float*)d_in[6];
    const float* b3 = (const float*)d_in[7];
    const float* W4 = (const float*)d_in[8];
    const float* b4 = (const float*)d_in[9];
    float* out = (float*)d_out;

    float *rp = nullptr, *part1 = nullptr;
    cudaGetSymbolAddress((void**)&rp, g_rp);
    cudaGetSymbolAddress((void**)&part1, g_part1);

    roipool_stage1<<<dim3(256, 12, 2), 128>>>(fm, coords, rp);
    fc1_partial<<<dim3(32, 32), 200>>>(rp, W1, part1);
    fused_tail<<<256, 512>>>(part1, b1, W2, b2, coords, W3, b3, W4, b4, out);
}